// round 1
// baseline (speedup 1.0000x reference)
#include <cuda_runtime.h>

// PointPillars pseudo-image scatter, implemented as inverse-map + coalesced gather.
// Output: (B=16, C=64, NY=400, NX=400) float32 = 655 MB, fully written each call.

#define B_   16
#define C_   64
#define NY_  400
#define NX_  400
#define PLANE  (NY_ * NX_)      // 160,000 pixels per (b) frame
#define NPIX   (B_ * PLANE)     // 2,560,000 total pixels

// Scratch: pixel -> voxel-row index (-1 = empty). 10.24 MB, static device array
// (allocation inside kernel_launch is forbidden; __device__ globals are allowed).
__device__ int g_map[NPIX];

// ---------------------------------------------------------------------------
// 1) init map to -1 (vectorized int4 stores)
// ---------------------------------------------------------------------------
__global__ void init_map_kernel() {
    int i = blockIdx.x * blockDim.x + threadIdx.x;
    if (i < NPIX / 4) {
        reinterpret_cast<int4*>(g_map)[i] = make_int4(-1, -1, -1, -1);
    }
}

// ---------------------------------------------------------------------------
// 2) scatter voxel row ids into the map. Indices are (b, z, y, x) int32 rows.
//    Cells are unique per batch -> no write conflicts, deterministic.
// ---------------------------------------------------------------------------
__global__ void scatter_map_kernel(const int* __restrict__ idx, int n) {
    int i = blockIdx.x * blockDim.x + threadIdx.x;
    if (i < n) {
        int4 v = reinterpret_cast<const int4*>(idx)[i];  // (b, z, y, x)
        g_map[v.x * PLANE + v.z * NX_ + v.w] = i;
    }
}

// ---------------------------------------------------------------------------
// 3) gather: each thread owns a quad of 4 consecutive x-pixels, loops over all
//    64 channels in chunks of 4. Per chunk: 4 predicated LDG.128 (one per
//    feature row), register transpose, 4 STG.128 (perfectly coalesced: the
//    warp covers 128 consecutive x positions per channel).
// ---------------------------------------------------------------------------
__global__ void __launch_bounds__(256) gather_kernel(
    const float* __restrict__ feat, float* __restrict__ out)
{
    int q = blockIdx.x * blockDim.x + threadIdx.x;   // quad id
    if (q >= NPIX / 4) return;

    int p   = q * 4;                                 // flat pixel index
    int b   = p / PLANE;
    int rem = p - b * PLANE;                         // y*NX + x, quad-aligned

    int4 m = *reinterpret_cast<const int4*>(g_map + p);

    const float* f0 = feat + (long long)m.x * C_;
    const float* f1 = feat + (long long)m.y * C_;
    const float* f2 = feat + (long long)m.z * C_;
    const float* f3 = feat + (long long)m.w * C_;

    float* obase = out + (long long)b * C_ * PLANE + rem;

    const float4 zero = make_float4(0.f, 0.f, 0.f, 0.f);

#pragma unroll 4
    for (int c = 0; c < C_; c += 4) {
        float4 a0 = (m.x >= 0) ? *reinterpret_cast<const float4*>(f0 + c) : zero;
        float4 a1 = (m.y >= 0) ? *reinterpret_cast<const float4*>(f1 + c) : zero;
        float4 a2 = (m.z >= 0) ? *reinterpret_cast<const float4*>(f2 + c) : zero;
        float4 a3 = (m.w >= 0) ? *reinterpret_cast<const float4*>(f3 + c) : zero;

        float4 o;
        o.x = a0.x; o.y = a1.x; o.z = a2.x; o.w = a3.x;
        *reinterpret_cast<float4*>(obase + (long long)(c + 0) * PLANE) = o;
        o.x = a0.y; o.y = a1.y; o.z = a2.y; o.w = a3.y;
        *reinterpret_cast<float4*>(obase + (long long)(c + 1) * PLANE) = o;
        o.x = a0.z; o.y = a1.z; o.z = a2.z; o.w = a3.z;
        *reinterpret_cast<float4*>(obase + (long long)(c + 2) * PLANE) = o;
        o.x = a0.w; o.y = a1.w; o.z = a2.w; o.w = a3.w;
        *reinterpret_cast<float4*>(obase + (long long)(c + 3) * PLANE) = o;
    }
}

// ---------------------------------------------------------------------------
// launch
// ---------------------------------------------------------------------------
extern "C" void kernel_launch(void* const* d_in, const int* in_sizes, int n_in,
                              void* d_out, int out_size) {
    const float* feat = (const float*)d_in[0];      // (N, 64) float32
    const int*   idx  = (const int*)d_in[1];        // (N, 4)  int32
    float*       out  = (float*)d_out;              // (16, 64, 400, 400)

    int n_vox = in_sizes[1] / 4;

    // 1) map = -1
    init_map_kernel<<<(NPIX / 4 + 255) / 256, 256>>>();
    // 2) map[pixel] = voxel row
    scatter_map_kernel<<<(n_vox + 255) / 256, 256>>>(idx, n_vox);
    // 3) coalesced gather into output (writes every element; no memset needed)
    gather_kernel<<<(NPIX / 4 + 255) / 256, 256>>>(feat, out);
}